// round 9
// baseline (speedup 1.0000x reference)
#include <cuda_runtime.h>
#include <cuda_bf16.h>

#define N_NODES 100000
#define N_EDGES 3200000
#define IN_F    128
#define HID     3
#define OUT_F   4

// Kernel 1: 15625 blocks. blockIdx%5==0 -> degree role (3125 blocks),
// else GEMV role (12500 blocks). Last K1_EPI arrivals run the scale epilogue.
#define K1_BLOCKS 15625
#define K1_EPI    128

// Kernel 2: 3125 blocks, 4 edges/thread. Last K2_EPI arrivals run the final
// epilogue.
#define K2_BLOCKS 3125
#define K2_EPI    256

// Scratch (device globals — zero-initialized at load; g_deg kept zero at entry
// by the scale epilogue resetting it every call)
__device__ float  g_deg[N_NODES];
__device__ float  g_dinv[N_NODES];
__device__ float4 g_sxw4[N_NODES];
__device__ float4 g_T4[N_NODES];

// Monotonic arrival counters (never reset; epoch derived from old % NBLOCKS;
// all increments of one replay complete before the next replay's kernel runs,
// so value-space epochs are contiguous). Unsigned wrap-safe via subtraction.
__device__ unsigned g_c1;
__device__ unsigned g_c2;

// Block-level arrive: all threads fence, leader increments, rank broadcast.
template <int NBLK>
__device__ __forceinline__ unsigned block_arrive(unsigned* ctr, unsigned* s_rank) {
    __threadfence();
    __syncthreads();
    if (threadIdx.x == 0) {
        unsigned old = atomicAdd(ctr, 1u);
        *s_rank = old;
    }
    __syncthreads();
    return *s_rank;
}

// Leader spins until counter reaches base + NBLK, then block proceeds.
template <int NBLK>
__device__ __forceinline__ void block_wait_all(volatile unsigned* ctr, unsigned base) {
    if (threadIdx.x == 0) {
        while (*ctr - base < (unsigned)NBLK) { __nanosleep(32); }
    }
    __syncthreads();
    __threadfence();
}

// ---------------------------------------------------------------------------
// 1) deg + GEMV (role-interleaved) + scale epilogue on last K1_EPI arrivals.
__global__ void k_fused1(const int* __restrict__ col,
                         const float* __restrict__ x,
                         const float* __restrict__ W) {
    __shared__ unsigned s_rank;
    int q = blockIdx.x / 5;
    int r = blockIdx.x % 5;
    int tid = threadIdx.x;

    if (r == 0) {
        // ---- degree role (block q of 3125): 4 edges/thread, int4 col load
        int e = (q * blockDim.x + tid) * 4;
        if (e + 3 < N_EDGES) {          // N_EDGES % 4 == 0 -> exact
            int4 c4 = *reinterpret_cast<const int4*>(col + e);
            if ((unsigned)c4.x < N_NODES) atomicAdd(&g_deg[c4.x], 1.0f);
            if ((unsigned)c4.y < N_NODES) atomicAdd(&g_deg[c4.y], 1.0f);
            if ((unsigned)c4.z < N_NODES) atomicAdd(&g_deg[c4.z], 1.0f);
            if ((unsigned)c4.w < N_NODES) atomicAdd(&g_deg[c4.w], 1.0f);
        }
    } else {
        // ---- GEMV role: warp-per-node, xw = x[node] @ W (128 -> 3), unscaled
        __shared__ float sW[IN_F * HID];
        for (int i = tid; i < IN_F * HID; i += blockDim.x) sW[i] = W[i];
        __syncthreads();

        int g = q * 4 + (r - 1);
        int node = g * 8 + (tid >> 5);
        int lane = tid & 31;
        if (node < N_NODES) {
            const float4 xv = *reinterpret_cast<const float4*>(
                x + (size_t)node * IN_F + lane * 4);
            int k0 = lane * 4;
            const float* w0 = &sW[(k0 + 0) * HID];
            const float* w1 = &sW[(k0 + 1) * HID];
            const float* w2 = &sW[(k0 + 2) * HID];
            const float* w3 = &sW[(k0 + 3) * HID];

            float a0 = xv.x * w0[0] + xv.y * w1[0] + xv.z * w2[0] + xv.w * w3[0];
            float a1 = xv.x * w0[1] + xv.y * w1[1] + xv.z * w2[1] + xv.w * w3[1];
            float a2 = xv.x * w0[2] + xv.y * w1[2] + xv.z * w2[2] + xv.w * w3[2];

            #pragma unroll
            for (int off = 16; off > 0; off >>= 1) {
                a0 += __shfl_down_sync(0xffffffffu, a0, off);
                a1 += __shfl_down_sync(0xffffffffu, a1, off);
                a2 += __shfl_down_sync(0xffffffffu, a2, off);
            }

            if (lane == 0) {
                g_sxw4[node] = make_float4(a0, a1, a2, 0.0f);
            }
        }
    }

    // ---- arrival + scale epilogue (last K1_EPI arrivals)
    unsigned old  = block_arrive<K1_BLOCKS>(&g_c1, &s_rank);
    unsigned rank = old % K1_BLOCKS;
    if (rank < K1_BLOCKS - K1_EPI) return;
    unsigned base = old - rank;
    block_wait_all<K1_BLOCKS>(&g_c1, base);

    // scale: dinv = rsqrt(deg+1); sxw *= dinv; T = sxw; deg = 0.
    // 25,000 float4-groups over K1_EPI*256 = 32768 threads (<=1 each).
    unsigned p   = rank - (K1_BLOCKS - K1_EPI);
    unsigned gid = p * blockDim.x + tid;
    if (gid < N_NODES / 4) {
        int i = gid * 4;
        float4 d4 = *reinterpret_cast<float4*>(&g_deg[i]);
        float4 dv;
        dv.x = rsqrtf(d4.x + 1.0f);
        dv.y = rsqrtf(d4.y + 1.0f);
        dv.z = rsqrtf(d4.z + 1.0f);
        dv.w = rsqrtf(d4.w + 1.0f);
        *reinterpret_cast<float4*>(&g_deg[i])  = make_float4(0.f, 0.f, 0.f, 0.f);
        *reinterpret_cast<float4*>(&g_dinv[i]) = dv;

        float4 s0 = g_sxw4[i + 0];
        float4 s1 = g_sxw4[i + 1];
        float4 s2 = g_sxw4[i + 2];
        float4 s3 = g_sxw4[i + 3];
        s0.x *= dv.x; s0.y *= dv.x; s0.z *= dv.x;
        s1.x *= dv.y; s1.y *= dv.y; s1.z *= dv.y;
        s2.x *= dv.z; s2.y *= dv.z; s2.z *= dv.z;
        s3.x *= dv.w; s3.y *= dv.w; s3.z *= dv.w;
        g_sxw4[i + 0] = s0;  g_T4[i + 0] = s0;
        g_sxw4[i + 1] = s1;  g_T4[i + 1] = s1;
        g_sxw4[i + 2] = s2;  g_T4[i + 2] = s2;
        g_sxw4[i + 3] = s3;  g_T4[i + 3] = s3;
    }
}

// ---------------------------------------------------------------------------
// 2) Edge scatter (4 edges/thread, int4 idx loads, LDG.128 gather + RED.128)
//    + final epilogue on last K2_EPI arrivals.
__global__ void k_fused2(const int* __restrict__ ei,
                         const float* __restrict__ b,
                         const float* __restrict__ Wout,
                         const float* __restrict__ bout,
                         float* __restrict__ out) {
    __shared__ unsigned s_rank;
    int tid = threadIdx.x;
    int e = (blockIdx.x * blockDim.x + tid) * 4;
    if (e + 3 < N_EDGES) {              // N_EDGES/4 == K2_BLOCKS*256 -> exact
        int4 r4 = *reinterpret_cast<const int4*>(ei + e);
        int4 c4 = *reinterpret_cast<const int4*>(ei + N_EDGES + e);
        if ((unsigned)r4.x < N_NODES && (unsigned)c4.x < N_NODES)
            atomicAdd(&g_T4[c4.x], g_sxw4[r4.x]);
        if ((unsigned)r4.y < N_NODES && (unsigned)c4.y < N_NODES)
            atomicAdd(&g_T4[c4.y], g_sxw4[r4.y]);
        if ((unsigned)r4.z < N_NODES && (unsigned)c4.z < N_NODES)
            atomicAdd(&g_T4[c4.z], g_sxw4[r4.z]);
        if ((unsigned)r4.w < N_NODES && (unsigned)c4.w < N_NODES)
            atomicAdd(&g_T4[c4.w], g_sxw4[r4.w]);
    }

    // ---- arrival + final epilogue (last K2_EPI arrivals)
    unsigned old  = block_arrive<K2_BLOCKS>(&g_c2, &s_rank);
    unsigned rank = old % K2_BLOCKS;
    if (rank < K2_BLOCKS - K2_EPI) return;
    unsigned base = old - rank;
    block_wait_all<K2_BLOCKS>(&g_c2, base);

    // final: h = relu(dinv*T + b); z = h @ Wout + bout; write (h, z).
    // 100,000 nodes over K2_EPI*256 = 65536 threads (~1.5 each).
    float b0 = __ldg(&b[0]), b1 = __ldg(&b[1]), b2 = __ldg(&b[2]);
    float w00 = __ldg(&Wout[0]),  w01 = __ldg(&Wout[1]),  w02 = __ldg(&Wout[2]),  w03 = __ldg(&Wout[3]);
    float w10 = __ldg(&Wout[4]),  w11 = __ldg(&Wout[5]),  w12 = __ldg(&Wout[6]),  w13 = __ldg(&Wout[7]);
    float w20 = __ldg(&Wout[8]),  w21 = __ldg(&Wout[9]),  w22 = __ldg(&Wout[10]), w23 = __ldg(&Wout[11]);
    float zb0 = __ldg(&bout[0]), zb1 = __ldg(&bout[1]), zb2 = __ldg(&bout[2]), zb3 = __ldg(&bout[3]);

    unsigned p = rank - (K2_BLOCKS - K2_EPI);
    const unsigned NT = K2_EPI * 256;
    for (unsigned i = p * blockDim.x + tid; i < N_NODES; i += NT) {
        float dinv = g_dinv[i];
        float4 tv  = g_T4[i];
        float h0 = fmaxf(tv.x * dinv + b0, 0.0f);
        float h1 = fmaxf(tv.y * dinv + b1, 0.0f);
        float h2 = fmaxf(tv.z * dinv + b2, 0.0f);

        unsigned hb = i * HID;
        out[hb + 0] = h0;
        out[hb + 1] = h1;
        out[hb + 2] = h2;

        float4 z;
        z.x = h0 * w00 + h1 * w10 + h2 * w20 + zb0;
        z.y = h0 * w01 + h1 * w11 + h2 * w21 + zb1;
        z.z = h0 * w02 + h1 * w12 + h2 * w22 + zb2;
        z.w = h0 * w03 + h1 * w13 + h2 * w23 + zb3;
        *reinterpret_cast<float4*>(out + (size_t)N_NODES * HID + (size_t)i * OUT_F) = z;
    }
}

extern "C" void kernel_launch(void* const* d_in, const int* in_sizes, int n_in,
                              void* d_out, int out_size) {
    // Bind inputs by element count (robust to ordering):
    // x=12,800,000  edge_index=6,400,000  W=384  b=3  Wout=12  bout=4
    const float* x    = nullptr;
    const int*   ei   = nullptr;
    const float* W    = nullptr;
    const float* b    = nullptr;
    const float* Wout = nullptr;
    const float* bout = nullptr;
    for (int i = 0; i < n_in; i++) {
        switch (in_sizes[i]) {
            case 12800000: x    = (const float*)d_in[i]; break;
            case 6400000:  ei   = (const int*)  d_in[i]; break;
            case 384:      W    = (const float*)d_in[i]; break;
            case 3:        b    = (const float*)d_in[i]; break;
            case 12:       Wout = (const float*)d_in[i]; break;
            case 4:        bout = (const float*)d_in[i]; break;
            default: break;
        }
    }

    float* out = (float*)d_out;

    k_fused1<<<K1_BLOCKS, 256>>>(ei + N_EDGES, x, W);
    k_fused2<<<K2_BLOCKS, 256>>>(ei, b, Wout, bout, out);
}